// round 1
// baseline (speedup 1.0000x reference)
#include <cuda_runtime.h>
#include <cuda_bf16.h>
#include <cstdint>

// ---------------- scratch (no cudaMalloc allowed) ----------------
__device__ float g_qkv[4096 * 3072]; // [B*T, 3*D]
__device__ float g_ctx[4096 * 1024]; // [B*T, D]

#define LOG2E 1.4426950408889634f

__device__ __forceinline__ float ex2f(float x) {
    float r;
    asm("ex2.approx.ftz.f32 %0, %1;" : "=f"(r) : "f"(x));
    return r;
}

// ---------------------------------------------------------------------------
// SGEMM: C[M,N] = A[M,K] @ B[N,K]^T + bias[N]
// A row-major [M][K], B row-major [N][K] (torch Linear weight convention).
// 128x128x8 tiles, 256 threads, 8x8 per-thread microtile.
// Requires M%128==0, N%128==0, K%8==0 (true for all our shapes).
// ---------------------------------------------------------------------------
__global__ void __launch_bounds__(256) sgemm_tn(
    const float* __restrict__ A, const float* __restrict__ B,
    const float* __restrict__ bias, float* __restrict__ C,
    int M, int N, int K)
{
    __shared__ float As[8][128];
    __shared__ float Bs[8][128];

    const int tid = threadIdx.x;
    const int bm = blockIdx.y * 128;
    const int bn = blockIdx.x * 128;

    const int lrow  = tid >> 1;        // 0..127
    const int lquad = (tid & 1) * 4;   // 0 or 4
    const int tx = tid & 15;           // 0..15
    const int ty = tid >> 4;           // 0..15

    float acc[8][8];
#pragma unroll
    for (int i = 0; i < 8; i++)
#pragma unroll
        for (int j = 0; j < 8; j++) acc[i][j] = 0.f;

    const float* Ag = A + (size_t)(bm + lrow) * K + lquad;
    const float* Bg = B + (size_t)(bn + lrow) * K + lquad;

    for (int k0 = 0; k0 < K; k0 += 8) {
        float4 a4 = *(const float4*)(Ag + k0);
        float4 b4 = *(const float4*)(Bg + k0);
        As[lquad + 0][lrow] = a4.x;
        As[lquad + 1][lrow] = a4.y;
        As[lquad + 2][lrow] = a4.z;
        As[lquad + 3][lrow] = a4.w;
        Bs[lquad + 0][lrow] = b4.x;
        Bs[lquad + 1][lrow] = b4.y;
        Bs[lquad + 2][lrow] = b4.z;
        Bs[lquad + 3][lrow] = b4.w;
        __syncthreads();

#pragma unroll
        for (int kk = 0; kk < 8; kk++) {
            float ar[8], br[8];
#pragma unroll
            for (int i = 0; i < 4; i++) {
                float4 v = *(const float4*)(&As[kk][ty * 8 + i * 4]);
                ar[i * 4 + 0] = v.x; ar[i * 4 + 1] = v.y; ar[i * 4 + 2] = v.z; ar[i * 4 + 3] = v.w;
            }
#pragma unroll
            for (int i = 0; i < 4; i++) {
                float4 v = *(const float4*)(&Bs[kk][tx * 8 + i * 4]);
                br[i * 4 + 0] = v.x; br[i * 4 + 1] = v.y; br[i * 4 + 2] = v.z; br[i * 4 + 3] = v.w;
            }
#pragma unroll
            for (int i = 0; i < 8; i++)
#pragma unroll
                for (int j = 0; j < 8; j++)
                    acc[i][j] = fmaf(ar[i], br[j], acc[i][j]);
        }
        __syncthreads();
    }

    float bj[8];
#pragma unroll
    for (int j = 0; j < 8; j++) bj[j] = bias[bn + tx * 8 + j];

#pragma unroll
    for (int i = 0; i < 8; i++) {
        float* crow = C + (size_t)(bm + ty * 8 + i) * N + bn + tx * 8;
#pragma unroll
        for (int j = 0; j < 8; j += 4) {
            float4 v;
            v.x = acc[i][j + 0] + bj[j + 0];
            v.y = acc[i][j + 1] + bj[j + 1];
            v.z = acc[i][j + 2] + bj[j + 2];
            v.w = acc[i][j + 3] + bj[j + 3];
            *(float4*)(crow + j) = v;
        }
    }
}

// ---------------------------------------------------------------------------
// Flash attention (causal), fp32 SIMT.
// grid = (T/64 q-tiles, B*H), block = 256.
// Each thread owns q-row r = tid/4 and 16 score/out columns c0 = (tid&3)*16.
// qkv layout: row (b*T+t), cols: q at h*64+d, k at 1024+h*64+d, v at 2048+h*64+d.
// ---------------------------------------------------------------------------
#define ATTN_SMEM ((64 * 64 + 3 * 64 * 68) * 4)

__global__ void __launch_bounds__(256) attn_kernel(
    const float* __restrict__ qkv, float* __restrict__ ctx)
{
    extern __shared__ float sm[];
    float* Qs = sm;              // [64][64]   q (pre-scaled by 0.125*log2e)
    float* Kt = Qs + 64 * 64;    // [64][68]   K transposed: [d][t]
    float* Vs = Kt + 64 * 68;    // [64][68]   V: [t][d]
    float* Ps = Vs + 64 * 68;    // [64][68]   softmax probs

    const int tid = threadIdx.x;
    const int q0 = blockIdx.x * 64;
    const int bh = blockIdx.y;
    const int b = bh >> 4, h = bh & 15;
    const size_t rowbase = (size_t)b * 2048;
    const int qcol = h * 64, kcol = 1024 + h * 64, vcol = 2048 + h * 64;

    const int r  = tid >> 2;         // 0..63
    const int c0 = (tid & 3) * 16;   // 0,16,32,48

    // load Q tile (scaled so softmax can use exp2)
    {
        const float qs = 0.125f * LOG2E;
        const float* gq = qkv + (rowbase + q0 + r) * 3072 + qcol + c0;
        float* sq = Qs + r * 64 + c0;
#pragma unroll
        for (int i = 0; i < 16; i += 4) {
            float4 v = *(const float4*)(gq + i);
            v.x *= qs; v.y *= qs; v.z *= qs; v.w *= qs;
            *(float4*)(sq + i) = v;
        }
    }

    float m = -1e30f, l = 0.f;
    float acc[16];
#pragma unroll
    for (int j = 0; j < 16; j++) acc[j] = 0.f;

    for (int k0 = 0; k0 <= q0; k0 += 64) {
        __syncthreads();  // previous tile's Kt/Vs reads done (also covers Q load)
        // load K (transposed) and V tiles
        {
            const float* gk = qkv + (rowbase + k0 + r) * 3072 + kcol + c0;
            const float* gv = qkv + (rowbase + k0 + r) * 3072 + vcol + c0;
#pragma unroll
            for (int i = 0; i < 16; i += 4) {
                float4 kv = *(const float4*)(gk + i);
                Kt[(c0 + i + 0) * 68 + r] = kv.x;
                Kt[(c0 + i + 1) * 68 + r] = kv.y;
                Kt[(c0 + i + 2) * 68 + r] = kv.z;
                Kt[(c0 + i + 3) * 68 + r] = kv.w;
                *(float4*)(Vs + r * 68 + c0 + i) = *(const float4*)(gv + i);
            }
        }
        __syncthreads();

        // S = Q K^T (log2-scaled)
        float s[16];
#pragma unroll
        for (int j = 0; j < 16; j++) s[j] = 0.f;
#pragma unroll 4
        for (int d = 0; d < 64; d++) {
            const float qv = Qs[r * 64 + d];
            const float* kr = Kt + d * 68 + c0;
#pragma unroll
            for (int j = 0; j < 16; j++) s[j] = fmaf(qv, kr[j], s[j]);
        }

        if (k0 == q0) {
#pragma unroll
            for (int j = 0; j < 16; j++)
                if (c0 + j > r) s[j] = -1e30f;
        }

        // online softmax (lanes {4g..4g+3} form one q-row group)
        float mt = s[0];
#pragma unroll
        for (int j = 1; j < 16; j++) mt = fmaxf(mt, s[j]);
        mt = fmaxf(mt, __shfl_xor_sync(0xffffffffu, mt, 1));
        mt = fmaxf(mt, __shfl_xor_sync(0xffffffffu, mt, 2));
        const float mnew = fmaxf(m, mt);
        const float corr = ex2f(m - mnew);
        float ls = 0.f;
#pragma unroll
        for (int j = 0; j < 16; j++) {
            float p = ex2f(s[j] - mnew);
            s[j] = p;
            ls += p;
        }
        ls += __shfl_xor_sync(0xffffffffu, ls, 1);
        ls += __shfl_xor_sync(0xffffffffu, ls, 2);
        l = l * corr + ls;
        m = mnew;
#pragma unroll
        for (int j = 0; j < 16; j++) acc[j] *= corr;

        // publish probs for this row (written/read within the same warp)
#pragma unroll
        for (int j = 0; j < 16; j += 4)
            *(float4*)(Ps + r * 68 + c0 + j) = make_float4(s[j], s[j + 1], s[j + 2], s[j + 3]);
        __syncwarp();

        // O += P @ V
#pragma unroll 4
        for (int j = 0; j < 64; j++) {
            const float p = Ps[r * 68 + j];
            const float* vr = Vs + j * 68 + c0;
#pragma unroll
            for (int cc = 0; cc < 16; cc++) acc[cc] = fmaf(p, vr[cc], acc[cc]);
        }
    }

    const float inv = 1.f / l;
    float* o = ctx + (rowbase + q0 + r) * 1024 + h * 64 + c0;
#pragma unroll
    for (int j = 0; j < 16; j += 4) {
        float4 v = make_float4(acc[j] * inv, acc[j + 1] * inv, acc[j + 2] * inv, acc[j + 3] * inv);
        *(float4*)(o + j) = v;
    }
}

// ---------------------------------------------------------------------------
extern "C" void kernel_launch(void* const* d_in, const int* in_sizes, int n_in,
                              void* d_out, int out_size)
{
    const float* x     = (const float*)d_in[0];  // [2,2048,1024]
    const float* w_in  = (const float*)d_in[1];  // [3072,1024]
    const float* b_in  = (const float*)d_in[2];  // [3072]
    const float* w_out = (const float*)d_in[3];  // [1024,1024]
    const float* b_out = (const float*)d_in[4];  // [1024]
    float* out = (float*)d_out;                  // [2,2048,1024]

    float *qkv = nullptr, *ctx = nullptr;
    cudaGetSymbolAddress((void**)&qkv, g_qkv);
    cudaGetSymbolAddress((void**)&ctx, g_ctx);

    cudaFuncSetAttribute(attn_kernel, cudaFuncAttributeMaxDynamicSharedMemorySize, ATTN_SMEM);

    // 1) packed QKV projection: [4096,3072]
    {
        dim3 grid(3072 / 128, 4096 / 128);
        sgemm_tn<<<grid, 256>>>(x, w_in, b_in, qkv, 4096, 3072, 1024);
    }
    // 2) causal flash attention -> ctx [4096,1024]
    {
        dim3 grid(2048 / 64, 32);  // (q-tiles, B*H)
        attn_kernel<<<grid, 256, ATTN_SMEM>>>(qkv, ctx);
    }
    // 3) output projection: [4096,1024]
    {
        dim3 grid(1024 / 128, 4096 / 128);
        sgemm_tn<<<grid, 256>>>(ctx, w_out, b_out, out, 4096, 1024, 1024);
    }
}

// round 2
// speedup vs baseline: 2.4126x; 2.4126x over previous
#include <cuda_runtime.h>
#include <cuda_bf16.h>
#include <cstdint>

// ---------------- scratch (no cudaMalloc allowed) ----------------
__device__ float g_qkv[4096 * 3072]; // [B*T, 3*D]
__device__ float g_ctx[4096 * 1024]; // [B*T, D]

#define LOG2E 1.4426950408889634f

__device__ __forceinline__ float ex2f(float x) {
    float r;
    asm("ex2.approx.ftz.f32 %0, %1;" : "=f"(r) : "f"(x));
    return r;
}

// ---------------------------------------------------------------------------
// SGEMM: C[M,N] = A[M,K] @ B[N,K]^T + bias[N]
// 128x128x8 tiles, 256 threads, 8x8 microtile, double-buffered smem.
// ---------------------------------------------------------------------------
__global__ void __launch_bounds__(256) sgemm_tn(
    const float* __restrict__ A, const float* __restrict__ B,
    const float* __restrict__ bias, float* __restrict__ C,
    int M, int N, int K)
{
    __shared__ float As[2][8][128];
    __shared__ float Bs[2][8][128];

    const int tid = threadIdx.x;
    const int bm = blockIdx.y * 128;
    const int bn = blockIdx.x * 128;

    const int lrow  = tid >> 1;        // 0..127
    const int lquad = (tid & 1) * 4;   // 0 or 4
    const int tx = tid & 15;           // 0..15
    const int ty = tid >> 4;           // 0..15

    float acc[8][8];
#pragma unroll
    for (int i = 0; i < 8; i++)
#pragma unroll
        for (int j = 0; j < 8; j++) acc[i][j] = 0.f;

    const float* Ag = A + (size_t)(bm + lrow) * K + lquad;
    const float* Bg = B + (size_t)(bn + lrow) * K + lquad;

    // prologue: stage 0
    {
        float4 a4 = *(const float4*)(Ag);
        float4 b4 = *(const float4*)(Bg);
        As[0][lquad + 0][lrow] = a4.x;
        As[0][lquad + 1][lrow] = a4.y;
        As[0][lquad + 2][lrow] = a4.z;
        As[0][lquad + 3][lrow] = a4.w;
        Bs[0][lquad + 0][lrow] = b4.x;
        Bs[0][lquad + 1][lrow] = b4.y;
        Bs[0][lquad + 2][lrow] = b4.z;
        Bs[0][lquad + 3][lrow] = b4.w;
    }
    __syncthreads();

    int st = 0;
    for (int k0 = 0; k0 < K; k0 += 8) {
        float4 a4n, b4n;
        const bool has = (k0 + 8) < K;
        if (has) {
            a4n = *(const float4*)(Ag + k0 + 8);
            b4n = *(const float4*)(Bg + k0 + 8);
        }

#pragma unroll
        for (int kk = 0; kk < 8; kk++) {
            float ar[8], br[8];
#pragma unroll
            for (int i = 0; i < 2; i++) {
                float4 v = *(const float4*)(&As[st][kk][ty * 8 + i * 4]);
                ar[i * 4 + 0] = v.x; ar[i * 4 + 1] = v.y; ar[i * 4 + 2] = v.z; ar[i * 4 + 3] = v.w;
            }
#pragma unroll
            for (int i = 0; i < 2; i++) {
                float4 v = *(const float4*)(&Bs[st][kk][tx * 8 + i * 4]);
                br[i * 4 + 0] = v.x; br[i * 4 + 1] = v.y; br[i * 4 + 2] = v.z; br[i * 4 + 3] = v.w;
            }
#pragma unroll
            for (int i = 0; i < 8; i++)
#pragma unroll
                for (int j = 0; j < 8; j++)
                    acc[i][j] = fmaf(ar[i], br[j], acc[i][j]);
        }

        if (has) {
            const int ns = st ^ 1;
            As[ns][lquad + 0][lrow] = a4n.x;
            As[ns][lquad + 1][lrow] = a4n.y;
            As[ns][lquad + 2][lrow] = a4n.z;
            As[ns][lquad + 3][lrow] = a4n.w;
            Bs[ns][lquad + 0][lrow] = b4n.x;
            Bs[ns][lquad + 1][lrow] = b4n.y;
            Bs[ns][lquad + 2][lrow] = b4n.z;
            Bs[ns][lquad + 3][lrow] = b4n.w;
        }
        __syncthreads();
        st ^= 1;
    }

    float bj[8];
#pragma unroll
    for (int j = 0; j < 8; j++) bj[j] = bias[bn + tx * 8 + j];

#pragma unroll
    for (int i = 0; i < 8; i++) {
        float* crow = C + (size_t)(bm + ty * 8 + i) * N + bn + tx * 8;
#pragma unroll
        for (int j = 0; j < 8; j += 4) {
            float4 v;
            v.x = acc[i][j + 0] + bj[j + 0];
            v.y = acc[i][j + 1] + bj[j + 1];
            v.z = acc[i][j + 2] + bj[j + 2];
            v.w = acc[i][j + 3] + bj[j + 3];
            *(float4*)(crow + j) = v;
        }
    }
}

// ---------------------------------------------------------------------------
// Flash attention (causal), fp32, register-blocked.
// Q-tile 128 rows, K-tile 64. 256 threads as 16(ty) x 16(tx).
// Thread (ty,tx): S/P microtile rows ty*8..+7, cols tx*4..+3;
//                 O microtile rows ty*8..+7, dims tx*4..+3.
// Shared: Qt[64][132] (Q^T, [d][q]), Kt[64][68] (K^T, [d][t]),
//         Vs[64][68] ([t][d]), Ps[128][68] ([q][t]).
// ---------------------------------------------------------------------------
#define TQ 128
#define ATTN_SMEM ((64 * 132 + 64 * 68 + 64 * 68 + 128 * 68) * 4)

__global__ void __launch_bounds__(256) attn_kernel(
    const float* __restrict__ qkv, float* __restrict__ ctx)
{
    extern __shared__ float sm[];
    float* Qt = sm;                 // [64][132]
    float* Kt = sm + 64 * 132;      // [64][68]
    float* Vs = Kt + 64 * 68;       // [64][68]
    float* Ps = Vs + 64 * 68;       // [128][68]

    const int tid = threadIdx.x;
    const int q0 = (gridDim.x - 1 - blockIdx.x) * TQ;   // heavy tiles first
    const int bh = blockIdx.y;
    const int b = bh >> 4, h = bh & 15;
    const size_t rowbase = (size_t)b * 2048;
    const int qcol = h * 64, kcol = 1024 + h * 64, vcol = 2048 + h * 64;

    const int ty = tid >> 4;   // 0..15 (8 q-rows each)
    const int tx = tid & 15;   // 0..15 (4 cols each)

    // ---- load Q tile transposed + pre-scaled ----
    {
        const float qs = 0.125f * LOG2E;
        const int rr = tid >> 1;              // 0..127
        const int cc = (tid & 1) * 32;        // 0 or 32
        const float* gq = qkv + (rowbase + q0 + rr) * 3072 + qcol + cc;
#pragma unroll
        for (int ii = 0; ii < 32; ii += 4) {
            float4 v = *(const float4*)(gq + ii);
            Qt[(cc + ii + 0) * 132 + rr] = v.x * qs;
            Qt[(cc + ii + 1) * 132 + rr] = v.y * qs;
            Qt[(cc + ii + 2) * 132 + rr] = v.z * qs;
            Qt[(cc + ii + 3) * 132 + rr] = v.w * qs;
        }
    }

    float m[8], l[8], o[8][4];
#pragma unroll
    for (int i = 0; i < 8; i++) {
        m[i] = -1e30f; l[i] = 0.f;
#pragma unroll
        for (int j = 0; j < 4; j++) o[i][j] = 0.f;
    }

    for (int k0 = 0; k0 <= q0 + 64; k0 += 64) {
        __syncthreads();   // prev tile Kt/Vs reads done (first iter: Q stores done)
        // ---- load K (transposed) and V tiles ----
        {
            const int rr = tid >> 2;           // 0..63
            const int cc = (tid & 3) * 16;     // 0,16,32,48
            const float* gk = qkv + (rowbase + k0 + rr) * 3072 + kcol + cc;
            const float* gv = qkv + (rowbase + k0 + rr) * 3072 + vcol + cc;
#pragma unroll
            for (int i = 0; i < 16; i += 4) {
                float4 kv = *(const float4*)(gk + i);
                Kt[(cc + i + 0) * 68 + rr] = kv.x;
                Kt[(cc + i + 1) * 68 + rr] = kv.y;
                Kt[(cc + i + 2) * 68 + rr] = kv.z;
                Kt[(cc + i + 3) * 68 + rr] = kv.w;
                *(float4*)(Vs + rr * 68 + cc + i) = *(const float4*)(gv + i);
            }
        }
        __syncthreads();

        // ---- S = Q K^T (log2-scaled), 8x4 microtile ----
        float s[8][4];
#pragma unroll
        for (int i = 0; i < 8; i++)
#pragma unroll
            for (int j = 0; j < 4; j++) s[i][j] = 0.f;

#pragma unroll 8
        for (int d = 0; d < 64; d++) {
            float4 a0 = *(const float4*)(Qt + d * 132 + ty * 8);
            float4 a1 = *(const float4*)(Qt + d * 132 + ty * 8 + 4);
            float4 bq = *(const float4*)(Kt + d * 68 + tx * 4);
            const float ar[8] = {a0.x, a0.y, a0.z, a0.w, a1.x, a1.y, a1.z, a1.w};
#pragma unroll
            for (int i = 0; i < 8; i++) {
                s[i][0] = fmaf(ar[i], bq.x, s[i][0]);
                s[i][1] = fmaf(ar[i], bq.y, s[i][1]);
                s[i][2] = fmaf(ar[i], bq.z, s[i][2]);
                s[i][3] = fmaf(ar[i], bq.w, s[i][3]);
            }
        }

        // ---- causal mask (only needed on last two tiles) ----
        if (k0 + 64 > q0) {
#pragma unroll
            for (int i = 0; i < 8; i++) {
                const int row = q0 + ty * 8 + i;
#pragma unroll
                for (int j = 0; j < 4; j++)
                    if (k0 + tx * 4 + j > row) s[i][j] = -1e30f;
            }
        }

        // ---- online softmax (row groups = 16 lanes sharing ty) ----
#pragma unroll
        for (int i = 0; i < 8; i++) {
            float mt = fmaxf(fmaxf(s[i][0], s[i][1]), fmaxf(s[i][2], s[i][3]));
            mt = fmaxf(mt, __shfl_xor_sync(0xffffffffu, mt, 1));
            mt = fmaxf(mt, __shfl_xor_sync(0xffffffffu, mt, 2));
            mt = fmaxf(mt, __shfl_xor_sync(0xffffffffu, mt, 4));
            mt = fmaxf(mt, __shfl_xor_sync(0xffffffffu, mt, 8));
            const float mnew = fmaxf(m[i], mt);
            const float corr = ex2f(m[i] - mnew);
            m[i] = mnew;
            float ls = 0.f;
#pragma unroll
            for (int j = 0; j < 4; j++) {
                float p = ex2f(s[i][j] - mnew);
                s[i][j] = p;
                ls += p;
            }
            ls += __shfl_xor_sync(0xffffffffu, ls, 1);
            ls += __shfl_xor_sync(0xffffffffu, ls, 2);
            ls += __shfl_xor_sync(0xffffffffu, ls, 4);
            ls += __shfl_xor_sync(0xffffffffu, ls, 8);
            l[i] = l[i] * corr + ls;
#pragma unroll
            for (int j = 0; j < 4; j++) o[i][j] *= corr;
        }

        // ---- publish P (row-major, float4 stores; consumers share the warp) ----
        __syncwarp();
#pragma unroll
        for (int i = 0; i < 8; i++)
            *(float4*)(Ps + (ty * 8 + i) * 68 + tx * 4) =
                make_float4(s[i][0], s[i][1], s[i][2], s[i][3]);
        __syncwarp();

        // ---- O += P @ V ----
#pragma unroll 2
        for (int k = 0; k < 64; k += 4) {
            float4 p4[8];
#pragma unroll
            for (int i = 0; i < 8; i++)
                p4[i] = *(const float4*)(Ps + (ty * 8 + i) * 68 + k);
#pragma unroll
            for (int kk = 0; kk < 4; kk++) {
                float4 bv = *(const float4*)(Vs + (k + kk) * 68 + tx * 4);
#pragma unroll
                for (int i = 0; i < 8; i++) {
                    const float pv = (kk == 0) ? p4[i].x : (kk == 1) ? p4[i].y
                                   : (kk == 2) ? p4[i].z : p4[i].w;
                    o[i][0] = fmaf(pv, bv.x, o[i][0]);
                    o[i][1] = fmaf(pv, bv.y, o[i][1]);
                    o[i][2] = fmaf(pv, bv.z, o[i][2]);
                    o[i][3] = fmaf(pv, bv.w, o[i][3]);
                }
            }
        }
    }

    // ---- epilogue ----
#pragma unroll
    for (int i = 0; i < 8; i++) {
        const float inv = 1.f / l[i];
        float4 v = make_float4(o[i][0] * inv, o[i][1] * inv, o[i][2] * inv, o[i][3] * inv);
        *(float4*)(ctx + (rowbase + q0 + ty * 8 + i) * 1024 + h * 64 + tx * 4) = v;
    }
}

// ---------------------------------------------------------------------------
extern "C" void kernel_launch(void* const* d_in, const int* in_sizes, int n_in,
                              void* d_out, int out_size)
{
    const float* x     = (const float*)d_in[0];  // [2,2048,1024]
    const float* w_in  = (const float*)d_in[1];  // [3072,1024]
    const float* b_in  = (const float*)d_in[2];  // [3072]
    const float* w_out = (const float*)d_in[3];  // [1024,1024]
    const float* b_out = (const float*)d_in[4];  // [1024]
    float* out = (float*)d_out;                  // [2,2048,1024]

    float *qkv = nullptr, *ctx = nullptr;
    cudaGetSymbolAddress((void**)&qkv, g_qkv);
    cudaGetSymbolAddress((void**)&ctx, g_ctx);

    cudaFuncSetAttribute(attn_kernel, cudaFuncAttributeMaxDynamicSharedMemorySize, ATTN_SMEM);

    // 1) packed QKV projection: [4096,3072]
    {
        dim3 grid(3072 / 128, 4096 / 128);
        sgemm_tn<<<grid, 256>>>(x, w_in, b_in, qkv, 4096, 3072, 1024);
    }
    // 2) causal flash attention -> ctx [4096,1024]
    {
        dim3 grid(2048 / TQ, 32);  // (q-tiles, B*H)
        attn_kernel<<<grid, 256, ATTN_SMEM>>>(qkv, ctx);
    }
    // 3) output projection: [4096,1024]
    {
        dim3 grid(1024 / 128, 4096 / 128);
        sgemm_tn<<<grid, 256>>>(ctx, w_out, b_out, out, 4096, 1024, 1024);
    }
}

// round 4
// speedup vs baseline: 4.0859x; 1.6936x over previous
#include <cuda_runtime.h>
#include <cstdint>

// ---------------- scratch (no cudaMalloc allowed) ----------------
__device__ float g_qkv[4096 * 3072]; // [B*T, 3*D] fp32
__device__ float g_ctx[4096 * 1024]; // [B*T, D]  tf32-rounded bits
__device__ float g_xa[4096 * 1024];  // x  as tf32 bits
__device__ float g_wa[3072 * 1024];  // w_in  as tf32 bits
__device__ float g_wb[1024 * 1024];  // w_out as tf32 bits

#define LOG2E 1.4426950408889634f

__device__ __forceinline__ float ex2f(float x) {
    float r;
    asm("ex2.approx.ftz.f32 %0, %1;" : "=f"(r) : "f"(x));
    return r;
}

__device__ __forceinline__ uint32_t f2tf(float f) {
    uint32_t r;
    asm("cvt.rna.tf32.f32 %0, %1;" : "=r"(r) : "f"(f));
    return r;
}

__device__ __forceinline__ uint32_t smem_u32(const void* p) {
    uint32_t a;
    asm("{ .reg .u64 t; cvta.to.shared.u64 t, %1; cvt.u32.u64 %0, t; }" : "=r"(a) : "l"(p));
    return a;
}

__device__ __forceinline__ void cp16(uint32_t dst, const void* src) {
    asm volatile("cp.async.cg.shared.global [%0], [%1], 16;" :: "r"(dst), "l"(src));
}

__device__ __forceinline__ void mma_tf32(float* c, const uint32_t* a, const uint32_t* b) {
    asm volatile(
        "mma.sync.aligned.m16n8k8.row.col.f32.tf32.tf32.f32 "
        "{%0,%1,%2,%3}, {%4,%5,%6,%7}, {%8,%9}, {%0,%1,%2,%3};"
        : "+f"(c[0]), "+f"(c[1]), "+f"(c[2]), "+f"(c[3])
        : "r"(a[0]), "r"(a[1]), "r"(a[2]), "r"(a[3]), "r"(b[0]), "r"(b[1]));
}

// ---------------------------------------------------------------------------
// Convert x / w_in / w_out to tf32 bits (round-to-nearest).
// ---------------------------------------------------------------------------
__global__ void __launch_bounds__(256) cvt_tf32(
    const float* __restrict__ x, const float* __restrict__ wi, const float* __restrict__ wo,
    float* __restrict__ xa, float* __restrict__ wa, float* __restrict__ wb)
{
    const int NX = 4096 * 1024 / 4, NI = 3072 * 1024 / 4, NO = 1024 * 1024 / 4;
    int i = blockIdx.x * blockDim.x + threadIdx.x;
    if (i >= NX + NI + NO) return;
    const float4* s;
    float4* d;
    if (i < NX)            { s = (const float4*)x + i;            d = (float4*)xa + i; }
    else if (i < NX + NI)  { s = (const float4*)wi + (i - NX);    d = (float4*)wa + (i - NX); }
    else                   { s = (const float4*)wo + (i - NX - NI); d = (float4*)wb + (i - NX - NI); }
    float4 v = *s;
    float4 o;
    o.x = __uint_as_float(f2tf(v.x));
    o.y = __uint_as_float(f2tf(v.y));
    o.z = __uint_as_float(f2tf(v.z));
    o.w = __uint_as_float(f2tf(v.w));
    *d = o;
}

// ---------------------------------------------------------------------------
// tf32 mma.sync GEMM: C[M,N] = A[M,K] @ B[N,K]^T + bias[N]
// A, B already tf32-rounded. CTA 256x128, BK=32, 8 warps (4m x 2n), warp 64x64.
// Smem rows padded to 36 floats -> all fragment LDS patterns conflict-free.
// Requires M%256==0, N%128==0, K%32==0.
// ---------------------------------------------------------------------------
#define SA_F (256 * 36)            // floats per A buffer
#define SB_F (128 * 36)
#define GEMM_SMEM ((2 * (SA_F + SB_F)) * 4)   // 110592 bytes

__global__ void __launch_bounds__(256) gemm_mma(
    const float* __restrict__ A, const float* __restrict__ B,
    const float* __restrict__ bias, float* __restrict__ C,
    int M, int N, int K)
{
    extern __shared__ float sm[];
    const int AOFF[2] = {0, SA_F + SB_F};
    const int BOFF[2] = {SA_F, 2 * SA_F + SB_F};

    const int tid = threadIdx.x, lane = tid & 31, wid = tid >> 5;
    const int bm = blockIdx.y * 256, bn = blockIdx.x * 128;
    const int m0 = (wid & 3) * 64, n0 = (wid >> 2) * 64;
    const int g = lane >> 2, t = lane & 3;

    float c[4][8][4];
#pragma unroll
    for (int mi = 0; mi < 4; mi++)
#pragma unroll
        for (int ni = 0; ni < 8; ni++)
#pragma unroll
            for (int j = 0; j < 4; j++) c[mi][ni][j] = 0.f;

    const int KT = K >> 5;
    const uint32_t sbase = smem_u32(sm);

    auto issue = [&](int kt, int b) {
        const float* Ag = A + (size_t)bm * K + kt * 32;
        const float* Bg = B + (size_t)bn * K + kt * 32;
        const uint32_t da = sbase + AOFF[b] * 4;
        const uint32_t db = sbase + BOFF[b] * 4;
#pragma unroll
        for (int i = 0; i < 8; i++) {
            const int idx = tid + i * 256;
            const int r = idx >> 3, c4 = idx & 7;
            cp16(da + r * 144 + c4 * 16, Ag + (size_t)r * K + c4 * 4);
        }
#pragma unroll
        for (int i = 0; i < 4; i++) {
            const int idx = tid + i * 256;
            const int r = idx >> 3, c4 = idx & 7;
            cp16(db + r * 144 + c4 * 16, Bg + (size_t)r * K + c4 * 4);
        }
    };

    issue(0, 0);
    asm volatile("cp.async.commit_group;" ::: "memory");

    for (int kt = 0; kt < KT; kt++) {
        const int buf = kt & 1;
        if (kt + 1 < KT) {
            issue(kt + 1, buf ^ 1);
            asm volatile("cp.async.commit_group;" ::: "memory");
            asm volatile("cp.async.wait_group 1;" ::: "memory");
        } else {
            asm volatile("cp.async.wait_group 0;" ::: "memory");
        }
        __syncthreads();

        const float* as = sm + AOFF[buf] + (m0 + g) * 36 + t;
        const float* bs = sm + BOFF[buf] + (n0 + g) * 36 + t;
#pragma unroll
        for (int ks = 0; ks < 4; ks++) {
            const int k = ks * 8;
            uint32_t a[4][4], b[8][2];
#pragma unroll
            for (int mi = 0; mi < 4; mi++) {
                a[mi][0] = __float_as_uint(as[(mi * 16 + 0) * 36 + k]);
                a[mi][1] = __float_as_uint(as[(mi * 16 + 8) * 36 + k]);
                a[mi][2] = __float_as_uint(as[(mi * 16 + 0) * 36 + k + 4]);
                a[mi][3] = __float_as_uint(as[(mi * 16 + 8) * 36 + k + 4]);
            }
#pragma unroll
            for (int ni = 0; ni < 8; ni++) {
                b[ni][0] = __float_as_uint(bs[ni * 8 * 36 + k]);
                b[ni][1] = __float_as_uint(bs[ni * 8 * 36 + k + 4]);
            }
#pragma unroll
            for (int mi = 0; mi < 4; mi++)
#pragma unroll
                for (int ni = 0; ni < 8; ni++)
                    mma_tf32(c[mi][ni], a[mi], b[ni]);
        }
        __syncthreads();
    }

    // epilogue
#pragma unroll
    for (int mi = 0; mi < 4; mi++) {
#pragma unroll
        for (int ni = 0; ni < 8; ni++) {
            const int row = bm + m0 + mi * 16 + g;
            const int col = bn + n0 + ni * 8 + t * 2;
            const float2 bb = *(const float2*)(bias + col);
            float2 v0 = make_float2(c[mi][ni][0] + bb.x, c[mi][ni][1] + bb.y);
            float2 v1 = make_float2(c[mi][ni][2] + bb.x, c[mi][ni][3] + bb.y);
            *(float2*)(C + (size_t)row * N + col) = v0;
            *(float2*)(C + (size_t)(row + 8) * N + col) = v1;
        }
    }
}

// ---------------------------------------------------------------------------
// Flash attention (causal), fp32, register-blocked. Epilogue writes tf32 bits.
// ---------------------------------------------------------------------------
#define TQ 128
#define ATTN_SMEM ((64 * 132 + 64 * 68 + 64 * 68 + 128 * 68) * 4)

__global__ void __launch_bounds__(256) attn_kernel(
    const float* __restrict__ qkv, float* __restrict__ ctx)
{
    extern __shared__ float smf[];
    float* Qt = smf;                // [64][132]
    float* Kt = smf + 64 * 132;     // [64][68]
    float* Vs = Kt + 64 * 68;       // [64][68]
    float* Ps = Vs + 64 * 68;       // [128][68]

    const int tid = threadIdx.x;
    const int q0 = (gridDim.x - 1 - blockIdx.x) * TQ;
    const int bh = blockIdx.y;
    const int b = bh >> 4, h = bh & 15;
    const size_t rowbase = (size_t)b * 2048;
    const int qcol = h * 64, kcol = 1024 + h * 64, vcol = 2048 + h * 64;

    const int ty = tid >> 4;
    const int tx = tid & 15;

    {
        const float qs = 0.125f * LOG2E;
        const int rr = tid >> 1;
        const int cc = (tid & 1) * 32;
        const float* gq = qkv + (rowbase + q0 + rr) * 3072 + qcol + cc;
#pragma unroll
        for (int ii = 0; ii < 32; ii += 4) {
            float4 v = *(const float4*)(gq + ii);
            Qt[(cc + ii + 0) * 132 + rr] = v.x * qs;
            Qt[(cc + ii + 1) * 132 + rr] = v.y * qs;
            Qt[(cc + ii + 2) * 132 + rr] = v.z * qs;
            Qt[(cc + ii + 3) * 132 + rr] = v.w * qs;
        }
    }

    float m[8], l[8], o[8][4];
#pragma unroll
    for (int i = 0; i < 8; i++) {
        m[i] = -1e30f; l[i] = 0.f;
#pragma unroll
        for (int j = 0; j < 4; j++) o[i][j] = 0.f;
    }

    for (int k0 = 0; k0 <= q0 + 64; k0 += 64) {
        __syncthreads();
        {
            const int rr = tid >> 2;
            const int cc = (tid & 3) * 16;
            const float* gk = qkv + (rowbase + k0 + rr) * 3072 + kcol + cc;
            const float* gv = qkv + (rowbase + k0 + rr) * 3072 + vcol + cc;
#pragma unroll
            for (int i = 0; i < 16; i += 4) {
                float4 kv = *(const float4*)(gk + i);
                Kt[(cc + i + 0) * 68 + rr] = kv.x;
                Kt[(cc + i + 1) * 68 + rr] = kv.y;
                Kt[(cc + i + 2) * 68 + rr] = kv.z;
                Kt[(cc + i + 3) * 68 + rr] = kv.w;
                *(float4*)(Vs + rr * 68 + cc + i) = *(const float4*)(gv + i);
            }
        }
        __syncthreads();

        float s[8][4];
#pragma unroll
        for (int i = 0; i < 8; i++)
#pragma unroll
            for (int j = 0; j < 4; j++) s[i][j] = 0.f;

#pragma unroll 8
        for (int d = 0; d < 64; d++) {
            float4 a0 = *(const float4*)(Qt + d * 132 + ty * 8);
            float4 a1 = *(const float4*)(Qt + d * 132 + ty * 8 + 4);
            float4 bq = *(const float4*)(Kt + d * 68 + tx * 4);
            const float ar[8] = {a0.x, a0.y, a0.z, a0.w, a1.x, a1.y, a1.z, a1.w};
#pragma unroll
            for (int i = 0; i < 8; i++) {
                s[i][0] = fmaf(ar[i], bq.x, s[i][0]);
                s[i][1] = fmaf(ar[i], bq.y, s[i][1]);
                s[i][2] = fmaf(ar[i], bq.z, s[i][2]);
                s[i][3] = fmaf(ar[i], bq.w, s[i][3]);
            }
        }

        if (k0 + 64 > q0) {
#pragma unroll
            for (int i = 0; i < 8; i++) {
                const int row = q0 + ty * 8 + i;
#pragma unroll
                for (int j = 0; j < 4; j++)
                    if (k0 + tx * 4 + j > row) s[i][j] = -1e30f;
            }
        }

#pragma unroll
        for (int i = 0; i < 8; i++) {
            float mt = fmaxf(fmaxf(s[i][0], s[i][1]), fmaxf(s[i][2], s[i][3]));
            mt = fmaxf(mt, __shfl_xor_sync(0xffffffffu, mt, 1));
            mt = fmaxf(mt, __shfl_xor_sync(0xffffffffu, mt, 2));
            mt = fmaxf(mt, __shfl_xor_sync(0xffffffffu, mt, 4));
            mt = fmaxf(mt, __shfl_xor_sync(0xffffffffu, mt, 8));
            const float mnew = fmaxf(m[i], mt);
            const float corr = ex2f(m[i] - mnew);
            m[i] = mnew;
            float ls = 0.f;
#pragma unroll
            for (int j = 0; j < 4; j++) {
                float p = ex2f(s[i][j] - mnew);
                s[i][j] = p;
                ls += p;
            }
            ls += __shfl_xor_sync(0xffffffffu, ls, 1);
            ls += __shfl_xor_sync(0xffffffffu, ls, 2);
            ls += __shfl_xor_sync(0xffffffffu, ls, 4);
            ls += __shfl_xor_sync(0xffffffffu, ls, 8);
            l[i] = l[i] * corr + ls;
#pragma unroll
            for (int j = 0; j < 4; j++) o[i][j] *= corr;
        }

        __syncwarp();
#pragma unroll
        for (int i = 0; i < 8; i++)
            *(float4*)(Ps + (ty * 8 + i) * 68 + tx * 4) =
                make_float4(s[i][0], s[i][1], s[i][2], s[i][3]);
        __syncwarp();

#pragma unroll 2
        for (int k = 0; k < 64; k += 4) {
            float4 p4[8];
#pragma unroll
            for (int i = 0; i < 8; i++)
                p4[i] = *(const float4*)(Ps + (ty * 8 + i) * 68 + k);
#pragma unroll
            for (int kk = 0; kk < 4; kk++) {
                float4 bv = *(const float4*)(Vs + (k + kk) * 68 + tx * 4);
#pragma unroll
                for (int i = 0; i < 8; i++) {
                    const float pv = (kk == 0) ? p4[i].x : (kk == 1) ? p4[i].y
                                   : (kk == 2) ? p4[i].z : p4[i].w;
                    o[i][0] = fmaf(pv, bv.x, o[i][0]);
                    o[i][1] = fmaf(pv, bv.y, o[i][1]);
                    o[i][2] = fmaf(pv, bv.z, o[i][2]);
                    o[i][3] = fmaf(pv, bv.w, o[i][3]);
                }
            }
        }
    }

    // epilogue: write ctx pre-rounded to tf32 so the out-projection can consume it
#pragma unroll
    for (int i = 0; i < 8; i++) {
        const float inv = 1.f / l[i];
        float4 v;
        v.x = __uint_as_float(f2tf(o[i][0] * inv));
        v.y = __uint_as_float(f2tf(o[i][1] * inv));
        v.z = __uint_as_float(f2tf(o[i][2] * inv));
        v.w = __uint_as_float(f2tf(o[i][3] * inv));
        *(float4*)(ctx + (rowbase + q0 + ty * 8 + i) * 1024 + h * 64 + tx * 4) = v;
    }
}

// ---------------------------------------------------------------------------
extern "C" void kernel_launch(void* const* d_in, const int* in_sizes, int n_in,
                              void* d_out, int out_size)
{
    const float* x     = (const float*)d_in[0];  // [2,2048,1024]
    const float* w_in  = (const float*)d_in[1];  // [3072,1024]
    const float* b_in  = (const float*)d_in[2];  // [3072]
    const float* w_out = (const float*)d_in[3];  // [1024,1024]
    const float* b_out = (const float*)d_in[4];  // [1024]
    float* out = (float*)d_out;                  // [2,2048,1024]

    float *qkv, *ctx, *xa, *wa, *wb;
    cudaGetSymbolAddress((void**)&qkv, g_qkv);
    cudaGetSymbolAddress((void**)&ctx, g_ctx);
    cudaGetSymbolAddress((void**)&xa, g_xa);
    cudaGetSymbolAddress((void**)&wa, g_wa);
    cudaGetSymbolAddress((void**)&wb, g_wb);

    cudaFuncSetAttribute(gemm_mma, cudaFuncAttributeMaxDynamicSharedMemorySize, GEMM_SMEM);
    cudaFuncSetAttribute(attn_kernel, cudaFuncAttributeMaxDynamicSharedMemorySize, ATTN_SMEM);

    // 0) round inputs to tf32
    {
        const int n4 = (4096 * 1024 + 3072 * 1024 + 1024 * 1024) / 4;
        cvt_tf32<<<(n4 + 255) / 256, 256>>>(x, w_in, w_out, xa, wa, wb);
    }
    // 1) packed QKV projection: [4096,3072] (tf32 mma.sync)
    {
        dim3 grid(3072 / 128, 4096 / 256);
        gemm_mma<<<grid, 256, GEMM_SMEM>>>(xa, wa, b_in, qkv, 4096, 3072, 1024);
    }
    // 2) causal flash attention -> ctx [4096,1024] (tf32-rounded)
    {
        dim3 grid(2048 / TQ, 32);
        attn_kernel<<<grid, 256, ATTN_SMEM>>>(qkv, ctx);
    }
    // 3) output projection: [4096,1024] (tf32 mma.sync)
    {
        dim3 grid(1024 / 128, 4096 / 256);
        gemm_mma<<<grid, 256, GEMM_SMEM>>>(ctx, wb, b_out, out, 4096, 1024, 1024);
    }
}

// round 5
// speedup vs baseline: 6.6231x; 1.6210x over previous
#include <cuda_runtime.h>
#include <cstdint>

// ---------------- scratch (no cudaMalloc allowed) ----------------
__device__ float g_qkv[4096 * 3072]; // [B*T, 3*D] fp32
__device__ float g_ctx[4096 * 1024]; // [B*T, D]  tf32-rounded bits
__device__ float g_xa[4096 * 1024];  // x  as tf32 bits
__device__ float g_wa[3072 * 1024];  // w_in  as tf32 bits
__device__ float g_wb[1024 * 1024];  // w_out as tf32 bits

#define LOG2E 1.4426950408889634f

__device__ __forceinline__ float ex2f(float x) {
    float r;
    asm("ex2.approx.ftz.f32 %0, %1;" : "=f"(r) : "f"(x));
    return r;
}

__device__ __forceinline__ uint32_t f2tf(float f) {
    uint32_t r;
    asm("cvt.rna.tf32.f32 %0, %1;" : "=r"(r) : "f"(f));
    return r;
}

__device__ __forceinline__ uint32_t smem_u32(const void* p) {
    uint32_t a;
    asm("{ .reg .u64 t; cvta.to.shared.u64 t, %1; cvt.u32.u64 %0, t; }" : "=r"(a) : "l"(p));
    return a;
}

__device__ __forceinline__ void cp16(uint32_t dst, const void* src) {
    asm volatile("cp.async.cg.shared.global [%0], [%1], 16;" :: "r"(dst), "l"(src));
}

__device__ __forceinline__ void mma_tf32(float* c, const uint32_t* a, const uint32_t* b) {
    asm volatile(
        "mma.sync.aligned.m16n8k8.row.col.f32.tf32.tf32.f32 "
        "{%0,%1,%2,%3}, {%4,%5,%6,%7}, {%8,%9}, {%0,%1,%2,%3};"
        : "+f"(c[0]), "+f"(c[1]), "+f"(c[2]), "+f"(c[3])
        : "r"(a[0]), "r"(a[1]), "r"(a[2]), "r"(a[3]), "r"(b[0]), "r"(b[1]));
}

// ---------------------------------------------------------------------------
// Convert x / w_in / w_out to tf32 bits (round-to-nearest).
// ---------------------------------------------------------------------------
__global__ void __launch_bounds__(256) cvt_tf32(
    const float* __restrict__ x, const float* __restrict__ wi, const float* __restrict__ wo,
    float* __restrict__ xa, float* __restrict__ wa, float* __restrict__ wb)
{
    const int NX = 4096 * 1024 / 4, NI = 3072 * 1024 / 4, NO = 1024 * 1024 / 4;
    int i = blockIdx.x * blockDim.x + threadIdx.x;
    if (i >= NX + NI + NO) return;
    const float4* s;
    float4* d;
    if (i < NX)            { s = (const float4*)x + i;            d = (float4*)xa + i; }
    else if (i < NX + NI)  { s = (const float4*)wi + (i - NX);    d = (float4*)wa + (i - NX); }
    else                   { s = (const float4*)wo + (i - NX - NI); d = (float4*)wb + (i - NX - NI); }
    float4 v = *s;
    float4 o;
    o.x = __uint_as_float(f2tf(v.x));
    o.y = __uint_as_float(f2tf(v.y));
    o.z = __uint_as_float(f2tf(v.z));
    o.w = __uint_as_float(f2tf(v.w));
    *d = o;
}

// ---------------------------------------------------------------------------
// tf32 mma.sync GEMM: C[M,N] = A[M,K] @ B[N,K]^T + bias[N]  (unchanged, R4)
// ---------------------------------------------------------------------------
#define SA_F (256 * 36)
#define SB_F (128 * 36)
#define GEMM_SMEM ((2 * (SA_F + SB_F)) * 4)

__global__ void __launch_bounds__(256) gemm_mma(
    const float* __restrict__ A, const float* __restrict__ B,
    const float* __restrict__ bias, float* __restrict__ C,
    int M, int N, int K)
{
    extern __shared__ float sm[];
    const int AOFF[2] = {0, SA_F + SB_F};
    const int BOFF[2] = {SA_F, 2 * SA_F + SB_F};

    const int tid = threadIdx.x, lane = tid & 31, wid = tid >> 5;
    const int bm = blockIdx.y * 256, bn = blockIdx.x * 128;
    const int m0 = (wid & 3) * 64, n0 = (wid >> 2) * 64;
    const int g = lane >> 2, t = lane & 3;

    float c[4][8][4];
#pragma unroll
    for (int mi = 0; mi < 4; mi++)
#pragma unroll
        for (int ni = 0; ni < 8; ni++)
#pragma unroll
            for (int j = 0; j < 4; j++) c[mi][ni][j] = 0.f;

    const int KT = K >> 5;
    const uint32_t sbase = smem_u32(sm);

    auto issue = [&](int kt, int b) {
        const float* Ag = A + (size_t)bm * K + kt * 32;
        const float* Bg = B + (size_t)bn * K + kt * 32;
        const uint32_t da = sbase + AOFF[b] * 4;
        const uint32_t db = sbase + BOFF[b] * 4;
#pragma unroll
        for (int i = 0; i < 8; i++) {
            const int idx = tid + i * 256;
            const int r = idx >> 3, c4 = idx & 7;
            cp16(da + r * 144 + c4 * 16, Ag + (size_t)r * K + c4 * 4);
        }
#pragma unroll
        for (int i = 0; i < 4; i++) {
            const int idx = tid + i * 256;
            const int r = idx >> 3, c4 = idx & 7;
            cp16(db + r * 144 + c4 * 16, Bg + (size_t)r * K + c4 * 4);
        }
    };

    issue(0, 0);
    asm volatile("cp.async.commit_group;" ::: "memory");

    for (int kt = 0; kt < KT; kt++) {
        const int buf = kt & 1;
        if (kt + 1 < KT) {
            issue(kt + 1, buf ^ 1);
            asm volatile("cp.async.commit_group;" ::: "memory");
            asm volatile("cp.async.wait_group 1;" ::: "memory");
        } else {
            asm volatile("cp.async.wait_group 0;" ::: "memory");
        }
        __syncthreads();

        const float* as = sm + AOFF[buf] + (m0 + g) * 36 + t;
        const float* bs = sm + BOFF[buf] + (n0 + g) * 36 + t;
#pragma unroll
        for (int ks = 0; ks < 4; ks++) {
            const int k = ks * 8;
            uint32_t a[4][4], b[8][2];
#pragma unroll
            for (int mi = 0; mi < 4; mi++) {
                a[mi][0] = __float_as_uint(as[(mi * 16 + 0) * 36 + k]);
                a[mi][1] = __float_as_uint(as[(mi * 16 + 8) * 36 + k]);
                a[mi][2] = __float_as_uint(as[(mi * 16 + 0) * 36 + k + 4]);
                a[mi][3] = __float_as_uint(as[(mi * 16 + 8) * 36 + k + 4]);
            }
#pragma unroll
            for (int ni = 0; ni < 8; ni++) {
                b[ni][0] = __float_as_uint(bs[ni * 8 * 36 + k]);
                b[ni][1] = __float_as_uint(bs[ni * 8 * 36 + k + 4]);
            }
#pragma unroll
            for (int mi = 0; mi < 4; mi++)
#pragma unroll
                for (int ni = 0; ni < 8; ni++)
                    mma_tf32(c[mi][ni], a[mi], b[ni]);
        }
        __syncthreads();
    }

#pragma unroll
    for (int mi = 0; mi < 4; mi++) {
#pragma unroll
        for (int ni = 0; ni < 8; ni++) {
            const int row = bm + m0 + mi * 16 + g;
            const int col = bn + n0 + ni * 8 + t * 2;
            const float2 bb = *(const float2*)(bias + col);
            float2 v0 = make_float2(c[mi][ni][0] + bb.x, c[mi][ni][1] + bb.y);
            float2 v1 = make_float2(c[mi][ni][2] + bb.x, c[mi][ni][3] + bb.y);
            *(float2*)(C + (size_t)row * N + col) = v0;
            *(float2*)(C + (size_t)(row + 8) * N + col) = v1;
        }
    }
}

// ---------------------------------------------------------------------------
// Flash attention (causal) with tf32 mma.sync for QK^T and PV.
// CTA: 128 q-rows, 8 warps; warp w owns q-rows [w*16, w*16+16), all 64 cols.
// kv-tile = 64. Smem rows stride 68 (==4 mod 32 -> fragment LDS conflict-free).
// ---------------------------------------------------------------------------
#define TQ 128
#define ATTN_SMEM ((128 * 68 + 64 * 68 + 64 * 68 + 128 * 68) * 4)   // 104448 B

__global__ void __launch_bounds__(256) attn_mma(
    const float* __restrict__ qkv, float* __restrict__ ctx)
{
    extern __shared__ float smf[];
    float* Qs = smf;              // [128][68] tf32 bits (scaled)
    float* Ks = smf + 128 * 68;   // [64][68]  tf32 bits
    float* Vt = Ks + 64 * 68;     // [64][68]  V^T [d][kv], tf32 bits
    float* Ps = Vt + 64 * 68;     // [128][68] P tf32 bits (warp-private strips)

    const int tid = threadIdx.x, lane = tid & 31, wid = tid >> 5;
    const int q0 = (int)(gridDim.x - 1 - blockIdx.x) * TQ;  // heavy tiles first
    const int bh = blockIdx.y;
    const int bb = bh >> 4, h = bh & 15;
    const size_t rowbase = (size_t)bb * 2048;
    const int qcol = h * 64, kcol = 1024 + h * 64, vcol = 2048 + h * 64;
    const int g = lane >> 2, t = lane & 3;

    // ---- load Q tile (scaled by 1/8*log2e, tf32-rounded) ----
    {
        const float qs = 0.125f * LOG2E;
        const int rr = tid >> 1, cc = (tid & 1) * 32;
        const float* gq = qkv + (rowbase + q0 + rr) * 3072 + qcol + cc;
        float* sq = Qs + rr * 68 + cc;
#pragma unroll
        for (int i = 0; i < 32; i += 4) {
            float4 v = *(const float4*)(gq + i);
            float4 w;
            w.x = __uint_as_float(f2tf(v.x * qs));
            w.y = __uint_as_float(f2tf(v.y * qs));
            w.z = __uint_as_float(f2tf(v.z * qs));
            w.w = __uint_as_float(f2tf(v.w * qs));
            *(float4*)(sq + i) = w;
        }
    }

    float m0 = -1e30f, m1 = -1e30f, l0 = 0.f, l1 = 0.f;
    float o[8][4];
#pragma unroll
    for (int ni = 0; ni < 8; ni++)
#pragma unroll
        for (int j = 0; j < 4; j++) o[ni][j] = 0.f;

    const int r0 = q0 + wid * 16 + g;   // rows of c0/c1 and c2/c3
    const int r1 = r0 + 8;
    const int prow = (wid * 16 + g) * 68;

    for (int k0 = 0; k0 <= q0 + 64; k0 += 64) {
        __syncthreads();   // prev tile's Ks/Vt reads done (1st iter: Q stores)
        // ---- load K, V tiles (tf32) ----
        {
            const int rr = tid >> 2, cc = (tid & 3) * 16;
            const float* gk = qkv + (rowbase + k0 + rr) * 3072 + kcol + cc;
            const float* gv = qkv + (rowbase + k0 + rr) * 3072 + vcol + cc;
            float* sk = Ks + rr * 68 + cc;
#pragma unroll
            for (int i = 0; i < 16; i += 4) {
                float4 kv = *(const float4*)(gk + i);
                float4 w;
                w.x = __uint_as_float(f2tf(kv.x));
                w.y = __uint_as_float(f2tf(kv.y));
                w.z = __uint_as_float(f2tf(kv.z));
                w.w = __uint_as_float(f2tf(kv.w));
                *(float4*)(sk + i) = w;
                float4 vv = *(const float4*)(gv + i);
                Vt[(cc + i + 0) * 68 + rr] = __uint_as_float(f2tf(vv.x));
                Vt[(cc + i + 1) * 68 + rr] = __uint_as_float(f2tf(vv.y));
                Vt[(cc + i + 2) * 68 + rr] = __uint_as_float(f2tf(vv.z));
                Vt[(cc + i + 3) * 68 + rr] = __uint_as_float(f2tf(vv.w));
            }
        }
        __syncthreads();

        // ---- S = Q K^T (log2-scaled) ----
        float s[8][4];
#pragma unroll
        for (int ni = 0; ni < 8; ni++)
#pragma unroll
            for (int j = 0; j < 4; j++) s[ni][j] = 0.f;
        {
            const float* aq = Qs + prow + t;
            const float* bk = Ks + g * 68 + t;
#pragma unroll
            for (int ks = 0; ks < 8; ks++) {
                uint32_t a[4];
                a[0] = __float_as_uint(aq[ks * 8]);
                a[1] = __float_as_uint(aq[8 * 68 + ks * 8]);
                a[2] = __float_as_uint(aq[ks * 8 + 4]);
                a[3] = __float_as_uint(aq[8 * 68 + ks * 8 + 4]);
#pragma unroll
                for (int ni = 0; ni < 8; ni++) {
                    uint32_t bf[2];
                    bf[0] = __float_as_uint(bk[ni * 8 * 68 + ks * 8]);
                    bf[1] = __float_as_uint(bk[ni * 8 * 68 + ks * 8 + 4]);
                    mma_tf32(s[ni], a, bf);
                }
            }
        }

        // ---- causal mask (per-warp skip) ----
        if (k0 + 64 > q0 + wid * 16) {
#pragma unroll
            for (int ni = 0; ni < 8; ni++) {
                const int col = k0 + ni * 8 + 2 * t;
                if (col > r0)     s[ni][0] = -1e30f;
                if (col + 1 > r0) s[ni][1] = -1e30f;
                if (col > r1)     s[ni][2] = -1e30f;
                if (col + 1 > r1) s[ni][3] = -1e30f;
            }
        }

        // ---- online softmax (rows r0, r1; quad reduction over t) ----
        float mt0 = -1e30f, mt1 = -1e30f;
#pragma unroll
        for (int ni = 0; ni < 8; ni++) {
            mt0 = fmaxf(mt0, fmaxf(s[ni][0], s[ni][1]));
            mt1 = fmaxf(mt1, fmaxf(s[ni][2], s[ni][3]));
        }
        mt0 = fmaxf(mt0, __shfl_xor_sync(0xffffffffu, mt0, 1));
        mt0 = fmaxf(mt0, __shfl_xor_sync(0xffffffffu, mt0, 2));
        mt1 = fmaxf(mt1, __shfl_xor_sync(0xffffffffu, mt1, 1));
        mt1 = fmaxf(mt1, __shfl_xor_sync(0xffffffffu, mt1, 2));
        const float mn0 = fmaxf(m0, mt0), mn1 = fmaxf(m1, mt1);
        const float cr0 = ex2f(m0 - mn0), cr1 = ex2f(m1 - mn1);
        m0 = mn0; m1 = mn1;

        float ls0 = 0.f, ls1 = 0.f;
#pragma unroll
        for (int ni = 0; ni < 8; ni++) {
            float p0 = ex2f(s[ni][0] - mn0);
            float p1 = ex2f(s[ni][1] - mn0);
            float p2 = ex2f(s[ni][2] - mn1);
            float p3 = ex2f(s[ni][3] - mn1);
            ls0 += p0 + p1;
            ls1 += p2 + p3;
            float2 v0, v1;
            v0.x = __uint_as_float(f2tf(p0));
            v0.y = __uint_as_float(f2tf(p1));
            v1.x = __uint_as_float(f2tf(p2));
            v1.y = __uint_as_float(f2tf(p3));
            *(float2*)(Ps + prow + ni * 8 + 2 * t) = v0;
            *(float2*)(Ps + prow + 8 * 68 + ni * 8 + 2 * t) = v1;
        }
        ls0 += __shfl_xor_sync(0xffffffffu, ls0, 1);
        ls0 += __shfl_xor_sync(0xffffffffu, ls0, 2);
        ls1 += __shfl_xor_sync(0xffffffffu, ls1, 1);
        ls1 += __shfl_xor_sync(0xffffffffu, ls1, 2);
        l0 = l0 * cr0 + ls0;
        l1 = l1 * cr1 + ls1;
#pragma unroll
        for (int ni = 0; ni < 8; ni++) {
            o[ni][0] *= cr0; o[ni][1] *= cr0;
            o[ni][2] *= cr1; o[ni][3] *= cr1;
        }

        __syncwarp();   // P strip is warp-private

        // ---- O += P @ V ----
        {
            const float* ap = Ps + prow + t;
            const float* bv = Vt + g * 68 + t;
#pragma unroll
            for (int ks = 0; ks < 8; ks++) {
                uint32_t a[4];
                a[0] = __float_as_uint(ap[ks * 8]);
                a[1] = __float_as_uint(ap[8 * 68 + ks * 8]);
                a[2] = __float_as_uint(ap[ks * 8 + 4]);
                a[3] = __float_as_uint(ap[8 * 68 + ks * 8 + 4]);
#pragma unroll
                for (int ni = 0; ni < 8; ni++) {
                    uint32_t bf[2];
                    bf[0] = __float_as_uint(bv[ni * 8 * 68 + ks * 8]);
                    bf[1] = __float_as_uint(bv[ni * 8 * 68 + ks * 8 + 4]);
                    mma_tf32(o[ni], a, bf);
                }
            }
        }
        __syncwarp();
    }

    // ---- epilogue: normalize, round to tf32 (out-proj consumes directly) ----
    const float i0 = 1.f / l0, i1 = 1.f / l1;
#pragma unroll
    for (int ni = 0; ni < 8; ni++) {
        float2 v0, v1;
        v0.x = __uint_as_float(f2tf(o[ni][0] * i0));
        v0.y = __uint_as_float(f2tf(o[ni][1] * i0));
        v1.x = __uint_as_float(f2tf(o[ni][2] * i1));
        v1.y = __uint_as_float(f2tf(o[ni][3] * i1));
        *(float2*)(ctx + (rowbase + r0) * 1024 + h * 64 + ni * 8 + 2 * t) = v0;
        *(float2*)(ctx + (rowbase + r1) * 1024 + h * 64 + ni * 8 + 2 * t) = v1;
    }
}

// ---------------------------------------------------------------------------
extern "C" void kernel_launch(void* const* d_in, const int* in_sizes, int n_in,
                              void* d_out, int out_size)
{
    const float* x     = (const float*)d_in[0];  // [2,2048,1024]
    const float* w_in  = (const float*)d_in[1];  // [3072,1024]
    const float* b_in  = (const float*)d_in[2];  // [3072]
    const float* w_out = (const float*)d_in[3];  // [1024,1024]
    const float* b_out = (const float*)d_in[4];  // [1024]
    float* out = (float*)d_out;                  // [2,2048,1024]

    float *qkv, *ctx, *xa, *wa, *wb;
    cudaGetSymbolAddress((void**)&qkv, g_qkv);
    cudaGetSymbolAddress((void**)&ctx, g_ctx);
    cudaGetSymbolAddress((void**)&xa, g_xa);
    cudaGetSymbolAddress((void**)&wa, g_wa);
    cudaGetSymbolAddress((void**)&wb, g_wb);

    cudaFuncSetAttribute(gemm_mma, cudaFuncAttributeMaxDynamicSharedMemorySize, GEMM_SMEM);
    cudaFuncSetAttribute(attn_mma, cudaFuncAttributeMaxDynamicSharedMemorySize, ATTN_SMEM);

    // 0) round inputs to tf32
    {
        const int n4 = (4096 * 1024 + 3072 * 1024 + 1024 * 1024) / 4;
        cvt_tf32<<<(n4 + 255) / 256, 256>>>(x, w_in, w_out, xa, wa, wb);
    }
    // 1) packed QKV projection: [4096,3072] (tf32 mma.sync)
    {
        dim3 grid(3072 / 128, 4096 / 256);
        gemm_mma<<<grid, 256, GEMM_SMEM>>>(xa, wa, b_in, qkv, 4096, 3072, 1024);
    }
    // 2) causal flash attention -> ctx [4096,1024] (tf32 mma.sync)
    {
        dim3 grid(2048 / TQ, 32);
        attn_mma<<<grid, 256, ATTN_SMEM>>>(qkv, ctx);
    }
    // 3) output projection: [4096,1024] (tf32 mma.sync)
    {
        dim3 grid(1024 / 128, 4096 / 256);
        gemm_mma<<<grid, 256, GEMM_SMEM>>>(ctx, wb, b_out, out, 4096, 1024, 1024);
    }
}